// round 2
// baseline (speedup 1.0000x reference)
#include <cuda_runtime.h>
#include <cuda_bf16.h>
#include <math.h>

#define SEQ 4096
#define DM  768
#define NH  12
#define HD  64

// Scratch (no cudaMalloc allowed): Q, K, V, CTX each [SEQ, DM] fp32
__device__ float g_q[SEQ * DM];
__device__ float g_k[SEQ * DM];
__device__ float g_v[SEQ * DM];
__device__ float g_ctx[SEQ * DM];

// ---------------------------------------------------------------------------
// 64x64x16 register-blocked SGEMM tile: C[M,N] = A[M,K] * B[K,N] (+bias)
// M=SEQ, N=K=DM. 256 threads, each computes 4x4.
// ---------------------------------------------------------------------------
__device__ __forceinline__ void sgemm64(const float* __restrict__ A,
                                        const float* __restrict__ B,
                                        float* __restrict__ C,
                                        const float* __restrict__ bias) {
    __shared__ float As[16][64];
    __shared__ float Bs[16][64];

    const int tid = threadIdx.x;
    const int tx = tid & 15;
    const int ty = tid >> 4;
    const int m0 = blockIdx.y * 64;
    const int n0 = blockIdx.x * 64;

    float acc[4][4] = {};

    for (int k0 = 0; k0 < DM; k0 += 16) {
        // Load A tile 64x16 (vectorized; transposed into As[k][m])
        {
            const int m = tid >> 2;           // 0..63
            const int k = (tid & 3) * 4;      // 0,4,8,12
            const float4 a4 = *(const float4*)(A + (size_t)(m0 + m) * DM + k0 + k);
            As[k + 0][m] = a4.x;
            As[k + 1][m] = a4.y;
            As[k + 2][m] = a4.z;
            As[k + 3][m] = a4.w;
        }
        // Load B tile 16x64 (vectorized, row-major)
        {
            const int k = tid >> 4;           // 0..15
            const int n = (tid & 15) * 4;     // 0..60
            *(float4*)&Bs[k][n] = *(const float4*)(B + (size_t)(k0 + k) * DM + n0 + n);
        }
        __syncthreads();

#pragma unroll
        for (int k = 0; k < 16; k++) {
            float a[4], b[4];
#pragma unroll
            for (int i = 0; i < 4; i++) a[i] = As[k][ty * 4 + i];
#pragma unroll
            for (int j = 0; j < 4; j++) b[j] = Bs[k][tx * 4 + j];
#pragma unroll
            for (int i = 0; i < 4; i++)
#pragma unroll
                for (int j = 0; j < 4; j++) acc[i][j] += a[i] * b[j];
        }
        __syncthreads();
    }

#pragma unroll
    for (int i = 0; i < 4; i++) {
        const int m = m0 + ty * 4 + i;
        const int n = n0 + tx * 4;
        float4 r;
        if (bias) {
            r.x = acc[i][0] + bias[n + 0];
            r.y = acc[i][1] + bias[n + 1];
            r.z = acc[i][2] + bias[n + 2];
            r.w = acc[i][3] + bias[n + 3];
        } else {
            r.x = acc[i][0]; r.y = acc[i][1]; r.z = acc[i][2]; r.w = acc[i][3];
        }
        *(float4*)(C + (size_t)m * DM + n) = r;
    }
}

// QKV projections fused via gridDim.z
__global__ __launch_bounds__(256) void qkv_kernel(const float* __restrict__ x,
                                                  const float* __restrict__ wq,
                                                  const float* __restrict__ wk,
                                                  const float* __restrict__ wv) {
    const float* W;
    float* O;
    if (blockIdx.z == 0)      { W = wq; O = g_q; }
    else if (blockIdx.z == 1) { W = wk; O = g_k; }
    else                      { W = wv; O = g_v; }
    sgemm64(x, W, O, nullptr);
}

__global__ __launch_bounds__(256) void out_proj_kernel(const float* __restrict__ wo,
                                                       const float* __restrict__ bo,
                                                       float* __restrict__ out) {
    sgemm64(g_ctx, wo, out, bo);
}

// ---------------------------------------------------------------------------
// Flash attention (causal), fp32. One CTA = 64 queries of one head.
// 8 warps; warp w owns rows w*8..w*8+7 of the score tile; lane owns
// columns {lane, lane+32}. P tile aliases the K buffer (padded to 65).
// ---------------------------------------------------------------------------
#define FLASH_SMEM ((64 * 64 + 64 * 65 + 64 * 64) * 4)

__global__ __launch_bounds__(256) void flash_kernel() {
    extern __shared__ float sm[];
    float* Qs = sm;                 // 64 x 64
    float* KP = sm + 64 * 64;       // 64 x 65  (K, then reused for P)
    float* Vs = KP + 64 * 65;       // 64 x 64

    const int tid = threadIdx.x;
    const int warp = tid >> 5;
    const int lane = tid & 31;
    const int qb = blockIdx.x;
    const int h = blockIdx.y;
    const int q0 = qb * 64;

    // Load Q tile: 64 rows x 16 float4 = 1024 slots, 4 per thread
#pragma unroll
    for (int i = 0; i < 4; i++) {
        const int idx = tid + i * 256;
        const int r = idx >> 4;           // 0..63
        const int d = (idx & 15) * 4;     // 0..60
        *(float4*)&Qs[r * 64 + d] =
            *(const float4*)(g_q + (size_t)(q0 + r) * DM + h * HD + d);
    }

    const int r0 = warp * 8;
    const int c0 = lane;
    const int c1 = lane + 32;

    float m_i[8], l_i[8], o0[8], o1[8];
#pragma unroll
    for (int r = 0; r < 8; r++) { m_i[r] = -1e30f; l_i[r] = 0.f; o0[r] = 0.f; o1[r] = 0.f; }

    for (int kb = 0; kb <= qb; kb++) {
        const int k0g = kb * 64;
        __syncthreads();   // prev iter done reading KP/Vs; Q load covered by next sync
        // Load K (into padded KP) and V: all 64 rows
#pragma unroll
        for (int i = 0; i < 4; i++) {
            const int idx = tid + i * 256;
            const int r = idx >> 4;           // 0..63
            const int d = (idx & 15) * 4;     // 0..60
            const float4 kv = *(const float4*)(g_k + (size_t)(k0g + r) * DM + h * HD + d);
            KP[r * 65 + d + 0] = kv.x;
            KP[r * 65 + d + 1] = kv.y;
            KP[r * 65 + d + 2] = kv.z;
            KP[r * 65 + d + 3] = kv.w;
            *(float4*)&Vs[r * 64 + d] =
                *(const float4*)(g_v + (size_t)(k0g + r) * DM + h * HD + d);
        }
        __syncthreads();

        // S = Q * K^T  (per lane: 8 rows x 2 cols)
        float s0[8], s1[8];
#pragma unroll
        for (int r = 0; r < 8; r++) { s0[r] = 0.f; s1[r] = 0.f; }
#pragma unroll 4
        for (int d = 0; d < 64; d++) {
            const float kv0 = KP[c0 * 65 + d];   // stride 65 -> conflict-free
            const float kv1 = KP[c1 * 65 + d];
#pragma unroll
            for (int r = 0; r < 8; r++) {
                const float qv = Qs[(r0 + r) * 64 + d];  // broadcast
                s0[r] += qv * kv0;
                s1[r] += qv * kv1;
            }
        }

        // Online softmax, rows fully within a warp
        const bool diag = (kb == qb);
#pragma unroll
        for (int r = 0; r < 8; r++) {
            float v0 = s0[r] * 0.125f;   // 1/sqrt(64)
            float v1 = s1[r] * 0.125f;
            if (diag) {
                const int qi = r0 + r;
                if (c0 > qi) v0 = -1e30f;
                if (c1 > qi) v1 = -1e30f;
            }
            float mx = fmaxf(v0, v1);
#pragma unroll
            for (int off = 16; off; off >>= 1)
                mx = fmaxf(mx, __shfl_xor_sync(0xffffffffu, mx, off));
            const float mnew = fmaxf(m_i[r], mx);
            const float e0 = __expf(v0 - mnew);
            const float e1 = __expf(v1 - mnew);
            float rs = e0 + e1;
#pragma unroll
            for (int off = 16; off; off >>= 1)
                rs += __shfl_xor_sync(0xffffffffu, rs, off);
            const float alpha = __expf(m_i[r] - mnew);
            m_i[r] = mnew;
            l_i[r] = l_i[r] * alpha + rs;
            o0[r] *= alpha;
            o1[r] *= alpha;
            s0[r] = e0;   // reuse as P
            s1[r] = e1;
        }

        __syncthreads();   // everyone done reading K
#pragma unroll
        for (int r = 0; r < 8; r++) {
            KP[(r0 + r) * 65 + c0] = s0[r];
            KP[(r0 + r) * 65 + c1] = s1[r];
        }
        __syncthreads();

        // O += P * V   (lane owns output dims {lane, lane+32})
#pragma unroll 4
        for (int c = 0; c < 64; c++) {
            const float v0 = Vs[c * 64 + lane];
            const float v1 = Vs[c * 64 + lane + 32];
#pragma unroll
            for (int r = 0; r < 8; r++) {
                const float pv = KP[(r0 + r) * 65 + c];  // broadcast
                o0[r] += pv * v0;
                o1[r] += pv * v1;
            }
        }
    }

    // Epilogue: normalize and write ctx
#pragma unroll
    for (int r = 0; r < 8; r++) {
        const float inv = 1.0f / l_i[r];
        const int row = q0 + r0 + r;
        g_ctx[(size_t)row * DM + h * HD + lane]      = o0[r] * inv;
        g_ctx[(size_t)row * DM + h * HD + lane + 32] = o1[r] * inv;
    }
}

// ---------------------------------------------------------------------------
extern "C" void kernel_launch(void* const* d_in, const int* in_sizes, int n_in,
                              void* d_out, int out_size) {
    const float* x  = (const float*)d_in[0];
    const float* wq = (const float*)d_in[1];
    const float* wk = (const float*)d_in[2];
    const float* wv = (const float*)d_in[3];
    const float* wo = (const float*)d_in[4];
    const float* bo = (const float*)d_in[5];
    float* out = (float*)d_out;

    // Idempotent; not a stream op, safe under graph capture.
    cudaFuncSetAttribute(flash_kernel, cudaFuncAttributeMaxDynamicSharedMemorySize,
                         FLASH_SMEM);

    qkv_kernel<<<dim3(DM / 64, SEQ / 64, 3), 256>>>(x, wq, wk, wv);
    flash_kernel<<<dim3(SEQ / 64, NH), 256, FLASH_SMEM>>>();
    out_proj_kernel<<<dim3(DM / 64, SEQ / 64), 256>>>(wo, bo, out);
}

// round 4
// speedup vs baseline: 1.1379x; 1.1379x over previous
#include <cuda_runtime.h>
#include <cuda_bf16.h>
#include <math.h>

#define SEQ 4096
#define DM  768
#define NH  12
#define HD  64

// Packed fp32x2 ops (sm_103a)
#define PACK2(out, lo, hi) asm("mov.b64 %0, {%1, %2};" : "=l"(out) : "f"(lo), "f"(hi))
#define UNPACK2(lo, hi, in) asm("mov.b64 {%0, %1}, %2;" : "=f"(lo), "=f"(hi) : "l"(in))
#define FMA2(d, a, b) asm("fma.rn.f32x2 %0, %1, %2, %3;" : "=l"(d) : "l"(a), "l"(b), "l"(d))
#define MUL2(d, a, b) asm("mul.rn.f32x2 %0, %1, %2;" : "=l"(d) : "l"(a), "l"(b))

typedef unsigned long long u64;

// Scratch: Q, K, V, CTX each [SEQ, DM] fp32
__device__ float g_q[SEQ * DM];
__device__ float g_k[SEQ * DM];
__device__ float g_v[SEQ * DM];
__device__ float g_ctx[SEQ * DM];

// ---------------------------------------------------------------------------
// 128x128x16 SGEMM, 256 threads, 8x8 per thread, packed-f32x2 accumulators
// C[M,N] = A[M,K] * B[K,N] (+bias).  A natural (broadcast), B natural (LDS.64)
// ---------------------------------------------------------------------------
#define AS_STRIDE 20
#define BS_STRIDE 132

__device__ __forceinline__ void gemm128(const float* __restrict__ A,
                                        const float* __restrict__ B,
                                        float* __restrict__ C,
                                        const float* __restrict__ bias) {
    __shared__ float As[128 * AS_STRIDE];
    __shared__ float Bs[16 * BS_STRIDE];

    const int tid = threadIdx.x;
    const int tx = tid & 15;
    const int ty = tid >> 4;
    const int m0 = blockIdx.y * 128;
    const int n0 = blockIdx.x * 128;

    u64 acc[8][4];
#pragma unroll
    for (int i = 0; i < 8; i++)
#pragma unroll
        for (int j = 0; j < 4; j++) acc[i][j] = 0ULL;

    for (int k0 = 0; k0 < DM; k0 += 16) {
        // A tile 128x16 (natural, stride 20): 512 float4, 2 per thread
#pragma unroll
        for (int t = 0; t < 2; t++) {
            const int idx = tid + t * 256;
            const int m = idx >> 2;
            const int kq = (idx & 3) * 4;
            *(float4*)&As[m * AS_STRIDE + kq] =
                *(const float4*)(A + (size_t)(m0 + m) * DM + k0 + kq);
        }
        // B tile 16x128 (natural, stride 132): 512 float4, 2 per thread
#pragma unroll
        for (int t = 0; t < 2; t++) {
            const int idx = tid + t * 256;
            const int kr = idx >> 5;
            const int nc = (idx & 31) * 4;
            *(float4*)&Bs[kr * BS_STRIDE + nc] =
                *(const float4*)(B + (size_t)(k0 + kr) * DM + n0 + nc);
        }
        __syncthreads();

#pragma unroll
        for (int k = 0; k < 16; k++) {
            u64 b2[4];
#pragma unroll
            for (int j = 0; j < 4; j++)
                b2[j] = *(const u64*)&Bs[k * BS_STRIDE + tx * 8 + j * 2];
#pragma unroll
            for (int i = 0; i < 8; i++) {
                const float av = As[(ty * 8 + i) * AS_STRIDE + k];
                u64 a2; PACK2(a2, av, av);
#pragma unroll
                for (int j = 0; j < 4; j++) FMA2(acc[i][j], a2, b2[j]);
            }
        }
        __syncthreads();
    }

#pragma unroll
    for (int i = 0; i < 8; i++) {
        const int m = m0 + ty * 8 + i;
        const int n = n0 + tx * 8;
        float o[8];
#pragma unroll
        for (int j = 0; j < 4; j++) UNPACK2(o[2 * j], o[2 * j + 1], acc[i][j]);
        if (bias) {
#pragma unroll
            for (int j = 0; j < 8; j++) o[j] += bias[n + j];
        }
        *(float4*)(C + (size_t)m * DM + n)     = make_float4(o[0], o[1], o[2], o[3]);
        *(float4*)(C + (size_t)m * DM + n + 4) = make_float4(o[4], o[5], o[6], o[7]);
    }
}

__global__ __launch_bounds__(256) void qkv_kernel(const float* __restrict__ x,
                                                  const float* __restrict__ wq,
                                                  const float* __restrict__ wk,
                                                  const float* __restrict__ wv) {
    const float* W;
    float* O;
    if (blockIdx.z == 0)      { W = wq; O = g_q; }
    else if (blockIdx.z == 1) { W = wk; O = g_k; }
    else                      { W = wv; O = g_v; }
    gemm128(x, W, O, nullptr);
}

__global__ __launch_bounds__(256) void out_proj_kernel(const float* __restrict__ wo,
                                                       const float* __restrict__ bo,
                                                       float* __restrict__ out) {
    gemm128(g_ctx, wo, out, bo);
}

// ---------------------------------------------------------------------------
// Flash attention (causal), fp32, packed f32x2.
// CTA = 128 queries x one head; tiles of 128 keys. 256 threads (16x16);
// thread (ty,tx) owns score rows ty*8..+8, cols tx*8..+8 (as 4 col-pairs),
// output rows ty*8..+8, dims tx*4..+4 (as 2 d-pairs).
// ---------------------------------------------------------------------------
#define BQ 128
#define BK 128
#define QS_STR 68    // Qs[128][68]  natural [r][d]
#define KT_STR 132   // Kt[64][132]  transposed [d][c]
#define VS_STR 68    // Vs[128][68]  natural [c][d]
#define PS_STR 132   // Ps[128][132] natural [r][c]
#define FLASH_SMEM ((BQ * QS_STR + HD * KT_STR + BK * VS_STR + BQ * PS_STR) * 4)

__global__ __launch_bounds__(256, 1) void flash_kernel() {
    extern __shared__ float sm[];
    float* Qs = sm;                        // 8704
    float* Kt = Qs + BQ * QS_STR;          // 8448
    float* Vs = Kt + HD * KT_STR;          // 8704
    float* Ps = Vs + BK * VS_STR;          // 16896

    const int tid = threadIdx.x;
    const int tx = tid & 15;
    const int ty = tid >> 4;
    const int qb = (gridDim.x - 1) - blockIdx.x;   // heavy CTAs first
    const int h = blockIdx.y;
    const int q0 = qb * BQ;

    // Load Q tile natural [r][d]: 128x64 = 2048 float4, 8 per thread
#pragma unroll
    for (int t = 0; t < 8; t++) {
        const int idx = tid + t * 256;
        const int r = idx >> 4;
        const int d4 = (idx & 15) * 4;
        *(float4*)&Qs[r * QS_STR + d4] =
            *(const float4*)(g_q + (size_t)(q0 + r) * DM + h * HD + d4);
    }

    float m_i[8], l_i[8];
    u64 O2[8][2];
#pragma unroll
    for (int i = 0; i < 8; i++) {
        m_i[i] = -1e30f; l_i[i] = 0.f; O2[i][0] = 0ULL; O2[i][1] = 0ULL;
    }

    for (int kb = 0; kb <= qb; kb++) {
        const int k0g = kb * BK;
        __syncthreads();   // prev iter done with Kt/Vs/Ps (and Q load on iter 0)

        // Load K transposed [d][c] and V natural [c][d]
#pragma unroll
        for (int t = 0; t < 8; t++) {
            const int idx = tid + t * 256;
            const int r = idx >> 4;
            const int d4 = (idx & 15) * 4;
            const float4 kv = *(const float4*)(g_k + (size_t)(k0g + r) * DM + h * HD + d4);
            Kt[(d4 + 0) * KT_STR + r] = kv.x;
            Kt[(d4 + 1) * KT_STR + r] = kv.y;
            Kt[(d4 + 2) * KT_STR + r] = kv.z;
            Kt[(d4 + 3) * KT_STR + r] = kv.w;
            *(float4*)&Vs[r * VS_STR + d4] =
                *(const float4*)(g_v + (size_t)(k0g + r) * DM + h * HD + d4);
        }
        __syncthreads();

        // S = Q K^T : acc packed over col-pairs
        u64 s2[8][4];
#pragma unroll
        for (int i = 0; i < 8; i++)
#pragma unroll
            for (int j = 0; j < 4; j++) s2[i][j] = 0ULL;

#pragma unroll 4
        for (int d = 0; d < HD; d++) {
            u64 k2[4];
#pragma unroll
            for (int j = 0; j < 4; j++)
                k2[j] = *(const u64*)&Kt[d * KT_STR + tx * 8 + j * 2];
#pragma unroll
            for (int i = 0; i < 8; i++) {
                const float qv = Qs[(ty * 8 + i) * QS_STR + d];
                u64 q2; PACK2(q2, qv, qv);
#pragma unroll
                for (int j = 0; j < 4; j++) FMA2(s2[i][j], q2, k2[j]);
            }
        }

        // Online softmax (rows within 16-lane half-warp groups)
        const bool diag = (kb == qb);
#pragma unroll
        for (int i = 0; i < 8; i++) {
            float s[8];
#pragma unroll
            for (int j = 0; j < 4; j++) UNPACK2(s[2 * j], s[2 * j + 1], s2[i][j]);
            const int rg = q0 + ty * 8 + i;
#pragma unroll
            for (int j = 0; j < 8; j++) {
                s[j] *= 0.125f;   // 1/sqrt(64)
                if (diag && (k0g + tx * 8 + j) > rg) s[j] = -1e30f;
            }
            float mx = s[0];
#pragma unroll
            for (int j = 1; j < 8; j++) mx = fmaxf(mx, s[j]);
#pragma unroll
            for (int off = 8; off; off >>= 1)
                mx = fmaxf(mx, __shfl_xor_sync(0xffffffffu, mx, off));
            const float mnew = fmaxf(m_i[i], mx);
            float rs = 0.f;
#pragma unroll
            for (int j = 0; j < 8; j++) { s[j] = __expf(s[j] - mnew); rs += s[j]; }
#pragma unroll
            for (int off = 8; off; off >>= 1)
                rs += __shfl_xor_sync(0xffffffffu, rs, off);
            const float alpha = __expf(m_i[i] - mnew);
            m_i[i] = mnew;
            l_i[i] = l_i[i] * alpha + rs;
            u64 a2; PACK2(a2, alpha, alpha);
            MUL2(O2[i][0], O2[i][0], a2);
            MUL2(O2[i][1], O2[i][1], a2);
            // store P row chunk (natural [r][c])
            *(float4*)&Ps[(ty * 8 + i) * PS_STR + tx * 8] =
                make_float4(s[0], s[1], s[2], s[3]);
            *(float4*)&Ps[(ty * 8 + i) * PS_STR + tx * 8 + 4] =
                make_float4(s[4], s[5], s[6], s[7]);
        }
        __syncthreads();   // P fully written

        // O += P V : packed over d-pairs, V natural LDS.64
#pragma unroll 2
        for (int c = 0; c < BK; c++) {
            const u64 v0 = *(const u64*)&Vs[c * VS_STR + tx * 4];
            const u64 v1 = *(const u64*)&Vs[c * VS_STR + tx * 4 + 2];
#pragma unroll
            for (int i = 0; i < 8; i++) {
                const float pv = Ps[(ty * 8 + i) * PS_STR + c];
                u64 p2; PACK2(p2, pv, pv);
                FMA2(O2[i][0], p2, v0);
                FMA2(O2[i][1], p2, v1);
            }
        }
    }

    // Epilogue
#pragma unroll
    for (int i = 0; i < 8; i++) {
        const float inv = 1.0f / l_i[i];
        float o[4];
        UNPACK2(o[0], o[1], O2[i][0]);
        UNPACK2(o[2], o[3], O2[i][1]);
        const int row = q0 + ty * 8 + i;
        *(float4*)(g_ctx + (size_t)row * DM + h * HD + tx * 4) =
            make_float4(o[0] * inv, o[1] * inv, o[2] * inv, o[3] * inv);
    }
}

// ---------------------------------------------------------------------------
extern "C" void kernel_launch(void* const* d_in, const int* in_sizes, int n_in,
                              void* d_out, int out_size) {
    const float* x  = (const float*)d_in[0];
    const float* wq = (const float*)d_in[1];
    const float* wk = (const float*)d_in[2];
    const float* wv = (const float*)d_in[3];
    const float* wo = (const float*)d_in[4];
    const float* bo = (const float*)d_in[5];
    float* out = (float*)d_out;

    cudaFuncSetAttribute(flash_kernel, cudaFuncAttributeMaxDynamicSharedMemorySize,
                         FLASH_SMEM);

    qkv_kernel<<<dim3(DM / 128, SEQ / 128, 3), 256>>>(x, wq, wk, wv);
    flash_kernel<<<dim3(SEQ / BQ, NH), 256, FLASH_SMEM>>>();
    out_proj_kernel<<<dim3(DM / 128, SEQ / 128), 256>>>(wo, bo, out);
}